// round 1
// baseline (speedup 1.0000x reference)
#include <cuda_runtime.h>

#define B 2
#define C 192
#define C3 576
#define SDIM 32
#define NPTS 32768           // 32^3
#define HEADS 4
#define CH 48
#define EPS 1e-12f

// ---------------- scratch (static device allocations) ----------------
__device__ float g_qkv[(size_t)B * C3 * NPTS];   // after 1x1 conv
__device__ float g_dw [(size_t)B * C3 * NPTS];   // after depthwise conv
__device__ float g_ob [(size_t)B * C  * NPTS];   // attention output (pre-proj)
__device__ float g_inv[B * 2 * C];               // 1/max(norm,eps): [b][chan 0..383]
__device__ float g_at [B * HEADS * CH * CH];     // attention logits / probs

// ---------------- 1x1x1 conv == GEMM:  Y[b,o,n] = sum_c W[o,c] X[b,c,n] + bias[o]
#define BM 64
#define BN 64
#define BK 16
__global__ __launch_bounds__(256) void gemm1x1(
    const float* __restrict__ Xall, const float* __restrict__ W,
    const float* __restrict__ bias, float* __restrict__ Yall,
    int O, int K, int N)
{
    const float* X = Xall + (size_t)blockIdx.z * K * N;
    float*       Y = Yall + (size_t)blockIdx.z * O * N;
    int n0 = blockIdx.x * BN;
    int o0 = blockIdx.y * BM;

    __shared__ float As[BK][BM];   // W^T tile
    __shared__ float Bs[BK][BN];   // X tile

    int tid = threadIdx.x;
    int tx = tid & 15, ty = tid >> 4;
    float acc[4][4] = {};

    for (int k0 = 0; k0 < K; k0 += BK) {
        {   // load W tile (64 x 16), transpose into As
            int r  = tid >> 2;
            int c4 = (tid & 3) * 4;
            float4 wv = *reinterpret_cast<const float4*>(&W[(size_t)(o0 + r) * K + k0 + c4]);
            As[c4 + 0][r] = wv.x; As[c4 + 1][r] = wv.y;
            As[c4 + 2][r] = wv.z; As[c4 + 3][r] = wv.w;
        }
        {   // load X tile (16 x 64)
            int r  = tid >> 4;
            int c4 = (tid & 15) * 4;
            *reinterpret_cast<float4*>(&Bs[r][c4]) =
                *reinterpret_cast<const float4*>(&X[(size_t)(k0 + r) * N + n0 + c4]);
        }
        __syncthreads();
        #pragma unroll
        for (int kk = 0; kk < BK; kk++) {
            float4 a = *reinterpret_cast<const float4*>(&As[kk][ty * 4]);
            float4 b = *reinterpret_cast<const float4*>(&Bs[kk][tx * 4]);
            float av[4] = {a.x, a.y, a.z, a.w};
            float bv[4] = {b.x, b.y, b.z, b.w};
            #pragma unroll
            for (int i = 0; i < 4; i++)
                #pragma unroll
                for (int j = 0; j < 4; j++)
                    acc[i][j] += av[i] * bv[j];
        }
        __syncthreads();
    }
    #pragma unroll
    for (int i = 0; i < 4; i++) {
        float bv = bias[o0 + ty * 4 + i];
        float4 o = {acc[i][0] + bv, acc[i][1] + bv, acc[i][2] + bv, acc[i][3] + bv};
        *reinterpret_cast<float4*>(&Y[(size_t)(o0 + ty * 4 + i) * N + n0 + tx * 4]) = o;
    }
}

// ---------------- depthwise 3x3x3, SAME (zero pad), per (b,c) volume ----------------
__global__ __launch_bounds__(256) void dwconv3(
    const float* __restrict__ in, const float* __restrict__ w,
    const float* __restrict__ bias, float* __restrict__ out)
{
    int bc = blockIdx.x;              // b*C3 + c
    int c  = bc % C3;
    const float* vol  = in  + (size_t)bc * NPTS;
    float*       ovol = out + (size_t)bc * NPTS;

    float wr[27];
    #pragma unroll
    for (int i = 0; i < 27; i++) wr[i] = w[c * 27 + i];
    float bv = bias[c];

    __shared__ float P[3][34][34];    // ring of z-planes with zero halo
    int tid = threadIdx.x;
    for (int i = tid; i < 3 * 34 * 34; i += 256) ((float*)P)[i] = 0.f;
    __syncthreads();
    for (int i = tid; i < 1024; i += 256)
        P[0][1 + (i >> 5)][1 + (i & 31)] = vol[i];
    __syncthreads();

    int tx4 = (tid & 7) * 4;          // 4 consecutive x per thread
    int ty  = tid >> 3;               // y row

    for (int z = 0; z < SDIM; z++) {
        int nb = (z + 1) % 3;
        if (z + 1 < SDIM) {
            for (int i = tid; i < 1024; i += 256)
                P[nb][1 + (i >> 5)][1 + (i & 31)] = vol[(size_t)(z + 1) * 1024 + i];
        } else {
            for (int i = tid; i < 34 * 34; i += 256) ((float*)P[nb])[i] = 0.f;
        }
        __syncthreads();
        int pm = (z + 2) % 3;         // plane z-1
        int pc = z % 3;               // plane z
        float a0 = bv, a1 = bv, a2 = bv, a3 = bv;
        #pragma unroll
        for (int dz = 0; dz < 3; dz++) {
            int pi = (dz == 0) ? pm : (dz == 1) ? pc : nb;
            #pragma unroll
            for (int dy = 0; dy < 3; dy++) {
                const float* row = &P[pi][ty + dy][tx4];
                float r0 = row[0], r1 = row[1], r2 = row[2],
                      r3 = row[3], r4 = row[4], r5 = row[5];
                float w0 = wr[dz * 9 + dy * 3 + 0];
                float w1 = wr[dz * 9 + dy * 3 + 1];
                float w2 = wr[dz * 9 + dy * 3 + 2];
                a0 += w0 * r0 + w1 * r1 + w2 * r2;
                a1 += w0 * r1 + w1 * r2 + w2 * r3;
                a2 += w0 * r2 + w1 * r3 + w2 * r4;
                a3 += w0 * r3 + w1 * r4 + w2 * r5;
            }
        }
        float4 o = {a0, a1, a2, a3};
        *reinterpret_cast<float4*>(&ovol[(size_t)z * 1024 + ty * 32 + tx4]) = o;
        __syncthreads();
    }
}

// ---------------- per-row 1/max(L2norm, eps) for q (chan 0..191) and k (192..383)
__global__ __launch_bounds__(256) void rownorm(const float* __restrict__ dw,
                                               float* __restrict__ inv)
{
    int idx = blockIdx.x;             // 0..767
    int b = idx / (2 * C), r = idx % (2 * C);
    const float* row = dw + ((size_t)b * C3 + r) * NPTS;
    float s = 0.f;
    for (int n = threadIdx.x; n < NPTS; n += 256) { float v = row[n]; s += v * v; }
    __shared__ float red[8];
    #pragma unroll
    for (int o = 16; o > 0; o >>= 1) s += __shfl_xor_sync(~0u, s, o);
    if ((threadIdx.x & 31) == 0) red[threadIdx.x >> 5] = s;
    __syncthreads();
    if (threadIdx.x < 8) {
        float v = red[threadIdx.x];
        #pragma unroll
        for (int o = 4; o > 0; o >>= 1) v += __shfl_xor_sync(0xffu, v, o);
        if (threadIdx.x == 0) inv[b * (2 * C) + r] = 1.0f / fmaxf(sqrtf(v), EPS);
    }
}

__global__ void zerok(float* p, int n)
{
    int i = blockIdx.x * blockDim.x + threadIdx.x;
    if (i < n) p[i] = 0.f;
}

// ---------------- attn_raw[b,h,c,e] += sum_{n-slab} q[c,n]*k[e,n]  (n split over blocks)
#define QKNT 32
#define NSPLIT 32
__global__ __launch_bounds__(256) void qk_gemm(const float* __restrict__ dw,
                                               float* __restrict__ attn)
{
    int b = blockIdx.z, h = blockIdx.y;
    int n0 = blockIdx.x * (NPTS / NSPLIT);          // 1024-wide slab
    const float* Q = dw + ((size_t)b * C3 + h * CH) * NPTS;
    const float* K = dw + ((size_t)b * C3 + C + h * CH) * NPTS;

    __shared__ float Qs[QKNT][49];
    __shared__ float Ks[QKNT][49];
    int tid = threadIdx.x;
    int tc = tid >> 4, te = tid & 15;
    float acc[3][3] = {};

    for (int nc = 0; nc < NPTS / NSPLIT; nc += QKNT) {
        int lane = tid & 31, wrp = tid >> 5;
        for (int cc = wrp; cc < CH; cc += 8) {
            Qs[lane][cc] = Q[(size_t)cc * NPTS + n0 + nc + lane];
            Ks[lane][cc] = K[(size_t)cc * NPTS + n0 + nc + lane];
        }
        __syncthreads();
        #pragma unroll
        for (int nn = 0; nn < QKNT; nn++) {
            float a0 = Qs[nn][tc * 3], a1 = Qs[nn][tc * 3 + 1], a2 = Qs[nn][tc * 3 + 2];
            float b0 = Ks[nn][te * 3], b1 = Ks[nn][te * 3 + 1], b2 = Ks[nn][te * 3 + 2];
            acc[0][0] += a0 * b0; acc[0][1] += a0 * b1; acc[0][2] += a0 * b2;
            acc[1][0] += a1 * b0; acc[1][1] += a1 * b1; acc[1][2] += a1 * b2;
            acc[2][0] += a2 * b0; acc[2][1] += a2 * b1; acc[2][2] += a2 * b2;
        }
        __syncthreads();
    }
    float* dst = attn + (size_t)(b * HEADS + h) * CH * CH;
    #pragma unroll
    for (int i = 0; i < 3; i++)
        #pragma unroll
        for (int j = 0; j < 3; j++)
            atomicAdd(&dst[(tc * 3 + i) * CH + te * 3 + j], acc[i][j]);
}

// ---------------- scale by inv norms + temperature, softmax over e (one warp per row)
__global__ void softmaxk(float* __restrict__ attn, const float* __restrict__ inv,
                         const float* __restrict__ temp)
{
    int gw = blockIdx.x * (blockDim.x / 32) + (threadIdx.x >> 5);
    if (gw >= B * HEADS * CH) return;
    int lane = threadIdx.x & 31;
    int c = gw % CH, bh = gw / CH, h = bh % HEADS, b = bh / HEADS;
    float* row = attn + (size_t)gw * CH;
    float iq = inv[b * (2 * C) + h * CH + c];
    float t  = temp[h];
    int e0 = lane, e1 = lane + 32;
    float x0 = row[e0] * iq * inv[b * (2 * C) + C + h * CH + e0] * t;
    float x1 = (e1 < CH) ? row[e1] * iq * inv[b * (2 * C) + C + h * CH + e1] * t : -1e30f;
    float m = fmaxf(x0, x1);
    #pragma unroll
    for (int o = 16; o > 0; o >>= 1) m = fmaxf(m, __shfl_xor_sync(~0u, m, o));
    float ex0 = expf(x0 - m);
    float ex1 = (e1 < CH) ? expf(x1 - m) : 0.f;
    float s = ex0 + ex1;
    #pragma unroll
    for (int o = 16; o > 0; o >>= 1) s += __shfl_xor_sync(~0u, s, o);
    float r = 1.f / s;
    row[e0] = ex0 * r;
    if (e1 < CH) row[e1] = ex1 * r;
}

// ---------------- out[b, h*48+c, n] = sum_e attn[c,e] * v[b, 384+h*48+e, n]
__global__ __launch_bounds__(128) void av_gemm(const float* __restrict__ dw,
                                               const float* __restrict__ attn,
                                               float* __restrict__ outb)
{
    int b = blockIdx.z, h = blockIdx.y;
    int n = blockIdx.x * 128 + threadIdx.x;
    __shared__ float As[CH][CH];      // transposed: As[e][c]
    const float* am = attn + (size_t)(b * HEADS + h) * CH * CH;
    for (int i = threadIdx.x; i < CH * CH; i += 128) {
        int c = i / CH, e = i % CH;
        As[e][c] = am[c * CH + e];
    }
    __syncthreads();
    const float* V = dw + ((size_t)b * C3 + 2 * C + h * CH) * NPTS;
    float acc[CH];
    #pragma unroll
    for (int c = 0; c < CH; c++) acc[c] = 0.f;
    #pragma unroll 4
    for (int e = 0; e < CH; e++) {
        float vv = V[(size_t)e * NPTS + n];
        #pragma unroll
        for (int c4 = 0; c4 < CH; c4 += 4) {
            float4 a = *reinterpret_cast<const float4*>(&As[e][c4]);
            acc[c4 + 0] += a.x * vv; acc[c4 + 1] += a.y * vv;
            acc[c4 + 2] += a.z * vv; acc[c4 + 3] += a.w * vv;
        }
    }
    float* O = outb + ((size_t)b * C + h * CH) * NPTS + n;
    #pragma unroll
    for (int c = 0; c < CH; c++) O[(size_t)c * NPTS] = acc[c];
}

// ---------------- launch ----------------
extern "C" void kernel_launch(void* const* d_in, const int* in_sizes, int n_in,
                              void* d_out, int out_size)
{
    const float* x      = (const float*)d_in[0];
    const float* qkv_w  = (const float*)d_in[1];
    const float* qkv_b  = (const float*)d_in[2];
    const float* dw_w   = (const float*)d_in[3];
    const float* dw_b   = (const float*)d_in[4];
    const float* proj_w = (const float*)d_in[5];
    const float* proj_b = (const float*)d_in[6];
    const float* temp   = (const float*)d_in[7];
    float* out = (float*)d_out;

    float *qkv, *dwp, *obp, *invp, *atp;
    cudaGetSymbolAddress((void**)&qkv,  g_qkv);
    cudaGetSymbolAddress((void**)&dwp,  g_dw);
    cudaGetSymbolAddress((void**)&obp,  g_ob);
    cudaGetSymbolAddress((void**)&invp, g_inv);
    cudaGetSymbolAddress((void**)&atp,  g_at);

    // 1) qkv 1x1 conv: [576 x 192] @ [192 x 32768] per batch
    gemm1x1<<<dim3(NPTS / BN, C3 / BM, B), 256>>>(x, qkv_w, qkv_b, qkv, C3, C, NPTS);
    // 2) depthwise 3x3x3
    dwconv3<<<B * C3, 256>>>(qkv, dw_w, dw_b, dwp);
    // 3) inverse L2 norms for q/k rows
    rownorm<<<B * 2 * C, 256>>>(dwp, invp);
    // 4) q @ k^T (raw), n-split with atomics
    zerok<<<(B * HEADS * CH * CH + 255) / 256, 256>>>(atp, B * HEADS * CH * CH);
    qk_gemm<<<dim3(NSPLIT, HEADS, B), 256>>>(dwp, atp);
    // 5) scale + softmax
    softmaxk<<<(B * HEADS * CH + 7) / 8, 256>>>(atp, invp, temp);
    // 6) attn @ v
    av_gemm<<<dim3(NPTS / 128, HEADS, B), 128>>>(dwp, atp, obp);
    // 7) proj 1x1 conv
    gemm1x1<<<dim3(NPTS / BN, C / BM, B), 256>>>(obp, proj_w, proj_b, out, C, C, NPTS);
}

// round 3
// speedup vs baseline: 1.4951x; 1.4951x over previous
#include <cuda_runtime.h>
#include <cuda_bf16.h>
#include <cstdint>

#define B 2
#define C 192
#define C3 576
#define SDIM 32
#define NPTS 32768           // 32^3
#define HEADS 4
#define CH 48
#define EPS 1e-12f

// ---------------- scratch (static device allocations) ----------------
__device__ float g_qkv[(size_t)B * C3 * NPTS];   // after 1x1 conv
__device__ float g_dw [(size_t)B * C3 * NPTS];   // after depthwise conv
__device__ float g_ob [(size_t)B * C  * NPTS];   // attention output (pre-proj)
__device__ float g_inv[B * 2 * C];               // 1/max(norm,eps)
__device__ float g_at [B * HEADS * CH * CH];     // attention logits / probs

// ================= mma.sync helpers (sm_80-compatible, works on base sm_103) ======
__device__ __forceinline__ uint32_t smem_u32(const void* p) {
    uint32_t a;
    asm("{ .reg .u64 t; cvta.to.shared.u64 t, %1; cvt.u32.u64 %0, t; }" : "=r"(a) : "l"(p));
    return a;
}
__device__ __forceinline__ void ldsm4(uint32_t* r, uint32_t a) {
    asm volatile("ldmatrix.sync.aligned.m8n8.x4.shared.b16 {%0,%1,%2,%3}, [%4];"
                 : "=r"(r[0]), "=r"(r[1]), "=r"(r[2]), "=r"(r[3]) : "r"(a));
}
__device__ __forceinline__ void ldsm2t(uint32_t* r, uint32_t a) {
    asm volatile("ldmatrix.sync.aligned.m8n8.x2.trans.shared.b16 {%0,%1}, [%2];"
                 : "=r"(r[0]), "=r"(r[1]) : "r"(a));
}
__device__ __forceinline__ void mma_bf16(float* d, const uint32_t* a, const uint32_t* b) {
    asm volatile(
        "mma.sync.aligned.m16n8k16.row.col.f32.bf16.bf16.f32 "
        "{%0,%1,%2,%3}, {%4,%5,%6,%7}, {%8,%9}, {%0,%1,%2,%3};"
        : "+f"(d[0]), "+f"(d[1]), "+f"(d[2]), "+f"(d[3])
        : "r"(a[0]), "r"(a[1]), "r"(a[2]), "r"(a[3]), "r"(b[0]), "r"(b[1]));
}
// fp32 -> bf16 hi + bf16(residual) for 4 values, packed as 2x uint32 each
__device__ __forceinline__ void cvt_hilo4(const float4 v, uint2& hi, uint2& lo) {
    __nv_bfloat162 h0 = __floats2bfloat162_rn(v.x, v.y);
    __nv_bfloat162 h1 = __floats2bfloat162_rn(v.z, v.w);
    float rx = v.x - __bfloat162float(h0.x);
    float ry = v.y - __bfloat162float(h0.y);
    float rz = v.z - __bfloat162float(h1.x);
    float rw = v.w - __bfloat162float(h1.y);
    __nv_bfloat162 l0 = __floats2bfloat162_rn(rx, ry);
    __nv_bfloat162 l1 = __floats2bfloat162_rn(rz, rw);
    hi.x = *reinterpret_cast<uint32_t*>(&h0); hi.y = *reinterpret_cast<uint32_t*>(&h1);
    lo.x = *reinterpret_cast<uint32_t*>(&l0); lo.y = *reinterpret_cast<uint32_t*>(&l1);
}

// ---------------- tensor-core 1x1 conv via mma.sync ----------------
// Y[b,o,n] = sum_c W[o,c] X[b,c,n] + bias[o]
// A = W tile [BM=64 x BK=32] (m-major, k contig, pitch 40 halves)
// B = X tile [BK=32 x BN=128] (k-major, n contig, pitch 136 halves)
// bf16 hi/lo split: acc += Ahi*Bhi + Ahi*Blo + Alo*Bhi
#define BMg 64
#define BNg 128
#define BKg 32
#define PA 40      // A pitch in halves
#define PB 136     // B pitch in halves

__global__ __launch_bounds__(256) void gemm_mma(
    const float* __restrict__ Xall, const float* __restrict__ W,
    const float* __restrict__ bias, float* __restrict__ Yall, int O)
{
    __shared__ __align__(16) uint16_t sAhi[BMg * PA], sAlo[BMg * PA];
    __shared__ __align__(16) uint16_t sBhi[BKg * PB], sBlo[BKg * PB];

    const int tid = threadIdx.x, wid = tid >> 5, lane = tid & 31;
    const int n0 = blockIdx.x * BNg;
    const int o0 = blockIdx.y * BMg;
    const float* X = Xall + (size_t)blockIdx.z * C * NPTS;
    float*       Y = Yall + (size_t)blockIdx.z * O * NPTS;

    const int warp_m = (wid >> 2) * 32;   // 2 warps in M
    const int warp_n = (wid & 3) * 32;    // 4 warps in N

    const uint32_t bAhi = smem_u32(sAhi), bAlo = smem_u32(sAlo);
    const uint32_t bBhi = smem_u32(sBhi), bBlo = smem_u32(sBlo);

    // ldmatrix lane addresses
    const uint32_t aOff = ((warp_m + (lane & 15)) * PA + (lane >> 4) * 8) * 2;
    const uint32_t bOff = ((lane & 15) * PB + warp_n) * 2;

    float acc[2][4][4] = {};

    for (int kc = 0; kc < C; kc += BKg) {
        // --- load W tile [64 x 32] -> A hi/lo
        #pragma unroll
        for (int q = 0; q < 2; q++) {
            int t  = tid + q * 256;            // 512 float4 total
            int m  = t >> 3, k4 = (t & 7) * 4;
            float4 wv = *reinterpret_cast<const float4*>(&W[(size_t)(o0 + m) * C + kc + k4]);
            uint2 hi, lo;
            cvt_hilo4(wv, hi, lo);
            *reinterpret_cast<uint2*>(&sAhi[m * PA + k4]) = hi;
            *reinterpret_cast<uint2*>(&sAlo[m * PA + k4]) = lo;
        }
        // --- load X tile [32 x 128] -> B hi/lo
        #pragma unroll
        for (int q = 0; q < 4; q++) {
            int t  = tid + q * 256;            // 1024 float4 total
            int c  = t >> 5, n4 = (t & 31) * 4;
            float4 xv = *reinterpret_cast<const float4*>(&X[(size_t)(kc + c) * NPTS + n0 + n4]);
            uint2 hi, lo;
            cvt_hilo4(xv, hi, lo);
            *reinterpret_cast<uint2*>(&sBhi[c * PB + n4]) = hi;
            *reinterpret_cast<uint2*>(&sBlo[c * PB + n4]) = lo;
        }
        __syncthreads();

        #pragma unroll
        for (int ks = 0; ks < 2; ks++) {       // two k16 steps per BK=32
            uint32_t Ahi[2][4], Alo[2][4], Bhi[4][2], Blo[4][2];
            #pragma unroll
            for (int i = 0; i < 2; i++) {
                uint32_t off = aOff + i * (16 * PA * 2) + ks * 32;
                ldsm4(Ahi[i], bAhi + off);
                ldsm4(Alo[i], bAlo + off);
            }
            #pragma unroll
            for (int j = 0; j < 4; j++) {
                uint32_t off = bOff + j * 16 + ks * (16 * PB * 2);
                ldsm2t(Bhi[j], bBhi + off);
                ldsm2t(Blo[j], bBlo + off);
            }
            #pragma unroll
            for (int i = 0; i < 2; i++)
                #pragma unroll
                for (int j = 0; j < 4; j++) {
                    mma_bf16(acc[i][j], Ahi[i], Bhi[j]);
                    mma_bf16(acc[i][j], Ahi[i], Blo[j]);
                    mma_bf16(acc[i][j], Alo[i], Bhi[j]);
                }
        }
        __syncthreads();
    }

    // epilogue: acc[i][j] regs c0..c3 -> (m, n), (m, n+1), (m+8, n), (m+8, n+1)
    #pragma unroll
    for (int i = 0; i < 2; i++) {
        int m = o0 + warp_m + i * 16 + (lane >> 2);
        float bv0 = bias[m], bv1 = bias[m + 8];
        #pragma unroll
        for (int j = 0; j < 4; j++) {
            int n = n0 + warp_n + j * 8 + (lane & 3) * 2;
            float2 r0 = {acc[i][j][0] + bv0, acc[i][j][1] + bv0};
            float2 r1 = {acc[i][j][2] + bv1, acc[i][j][3] + bv1};
            *reinterpret_cast<float2*>(&Y[(size_t)m * NPTS + n]) = r0;
            *reinterpret_cast<float2*>(&Y[(size_t)(m + 8) * NPTS + n]) = r1;
        }
    }
}

// ---------------- depthwise 3x3x3, SAME (zero pad), per (b,c) volume ----------------
__global__ __launch_bounds__(256) void dwconv3(
    const float* __restrict__ in, const float* __restrict__ w,
    const float* __restrict__ bias, float* __restrict__ out)
{
    int bc = blockIdx.x;
    int c  = bc % C3;
    const float* vol  = in  + (size_t)bc * NPTS;
    float*       ovol = out + (size_t)bc * NPTS;

    float wr[27];
    #pragma unroll
    for (int i = 0; i < 27; i++) wr[i] = w[c * 27 + i];
    float bv = bias[c];

    __shared__ float P[3][34][34];
    int tid = threadIdx.x;
    for (int i = tid; i < 3 * 34 * 34; i += 256) ((float*)P)[i] = 0.f;
    __syncthreads();
    for (int i = tid; i < 1024; i += 256)
        P[0][1 + (i >> 5)][1 + (i & 31)] = vol[i];
    __syncthreads();

    int tx4 = (tid & 7) * 4;
    int ty  = tid >> 3;

    for (int z = 0; z < SDIM; z++) {
        int nb = (z + 1) % 3;
        if (z + 1 < SDIM) {
            for (int i = tid; i < 1024; i += 256)
                P[nb][1 + (i >> 5)][1 + (i & 31)] = vol[(size_t)(z + 1) * 1024 + i];
        } else {
            for (int i = tid; i < 34 * 34; i += 256) ((float*)P[nb])[i] = 0.f;
        }
        __syncthreads();
        int pm = (z + 2) % 3;
        int pc = z % 3;
        float a0 = bv, a1 = bv, a2 = bv, a3 = bv;
        #pragma unroll
        for (int dz = 0; dz < 3; dz++) {
            int pi = (dz == 0) ? pm : (dz == 1) ? pc : nb;
            #pragma unroll
            for (int dy = 0; dy < 3; dy++) {
                const float* row = &P[pi][ty + dy][tx4];
                float r0 = row[0], r1 = row[1], r2 = row[2],
                      r3 = row[3], r4 = row[4], r5 = row[5];
                float w0 = wr[dz * 9 + dy * 3 + 0];
                float w1 = wr[dz * 9 + dy * 3 + 1];
                float w2 = wr[dz * 9 + dy * 3 + 2];
                a0 += w0 * r0 + w1 * r1 + w2 * r2;
                a1 += w0 * r1 + w1 * r2 + w2 * r3;
                a2 += w0 * r2 + w1 * r3 + w2 * r4;
                a3 += w0 * r3 + w1 * r4 + w2 * r5;
            }
        }
        float4 o = {a0, a1, a2, a3};
        *reinterpret_cast<float4*>(&ovol[(size_t)z * 1024 + ty * 32 + tx4]) = o;
        __syncthreads();
    }
}

// ---------------- per-row 1/max(L2norm, eps) ----------------
__global__ __launch_bounds__(256) void rownorm(const float* __restrict__ dw,
                                               float* __restrict__ inv)
{
    int idx = blockIdx.x;
    int b = idx / (2 * C), r = idx % (2 * C);
    const float* row = dw + ((size_t)b * C3 + r) * NPTS;
    float s = 0.f;
    for (int n = threadIdx.x; n < NPTS; n += 256) { float v = row[n]; s += v * v; }
    __shared__ float red[8];
    #pragma unroll
    for (int o = 16; o > 0; o >>= 1) s += __shfl_xor_sync(~0u, s, o);
    if ((threadIdx.x & 31) == 0) red[threadIdx.x >> 5] = s;
    __syncthreads();
    if (threadIdx.x < 8) {
        float v = red[threadIdx.x];
        #pragma unroll
        for (int o = 4; o > 0; o >>= 1) v += __shfl_xor_sync(0xffu, v, o);
        if (threadIdx.x == 0) inv[b * (2 * C) + r] = 1.0f / fmaxf(sqrtf(v), EPS);
    }
}

__global__ void zerok(float* p, int n)
{
    int i = blockIdx.x * blockDim.x + threadIdx.x;
    if (i < n) p[i] = 0.f;
}

// ---------------- attn_raw[b,h,c,e] += sum_{n-slab} q[c,n]*k[e,n] ----------------
#define QKNT 32
#define NSPLIT 32
__global__ __launch_bounds__(256) void qk_gemm(const float* __restrict__ dw,
                                               float* __restrict__ attn)
{
    int b = blockIdx.z, h = blockIdx.y;
    int n0 = blockIdx.x * (NPTS / NSPLIT);
    const float* Q = dw + ((size_t)b * C3 + h * CH) * NPTS;
    const float* K = dw + ((size_t)b * C3 + C + h * CH) * NPTS;

    __shared__ float Qs[QKNT][49];
    __shared__ float Ks[QKNT][49];
    int tid = threadIdx.x;
    int tc = tid >> 4, te = tid & 15;
    float acc[3][3] = {};

    for (int nc = 0; nc < NPTS / NSPLIT; nc += QKNT) {
        int lane = tid & 31, wrp = tid >> 5;
        for (int cc = wrp; cc < CH; cc += 8) {
            Qs[lane][cc] = Q[(size_t)cc * NPTS + n0 + nc + lane];
            Ks[lane][cc] = K[(size_t)cc * NPTS + n0 + nc + lane];
        }
        __syncthreads();
        #pragma unroll
        for (int nn = 0; nn < QKNT; nn++) {
            float a0 = Qs[nn][tc * 3], a1 = Qs[nn][tc * 3 + 1], a2 = Qs[nn][tc * 3 + 2];
            float b0 = Ks[nn][te * 3], b1 = Ks[nn][te * 3 + 1], b2 = Ks[nn][te * 3 + 2];
            acc[0][0] += a0 * b0; acc[0][1] += a0 * b1; acc[0][2] += a0 * b2;
            acc[1][0] += a1 * b0; acc[1][1] += a1 * b1; acc[1][2] += a1 * b2;
            acc[2][0] += a2 * b0; acc[2][1] += a2 * b1; acc[2][2] += a2 * b2;
        }
        __syncthreads();
    }
    float* dst = attn + (size_t)(b * HEADS + h) * CH * CH;
    #pragma unroll
    for (int i = 0; i < 3; i++)
        #pragma unroll
        for (int j = 0; j < 3; j++)
            atomicAdd(&dst[(tc * 3 + i) * CH + te * 3 + j], acc[i][j]);
}

// ---------------- scale + softmax ----------------
__global__ void softmaxk(float* __restrict__ attn, const float* __restrict__ inv,
                         const float* __restrict__ temp)
{
    int gw = blockIdx.x * (blockDim.x / 32) + (threadIdx.x >> 5);
    if (gw >= B * HEADS * CH) return;
    int lane = threadIdx.x & 31;
    int c = gw % CH, bh = gw / CH, h = bh % HEADS, b = bh / HEADS;
    float* row = attn + (size_t)gw * CH;
    float iq = inv[b * (2 * C) + h * CH + c];
    float t  = temp[h];
    int e0 = lane, e1 = lane + 32;
    float x0 = row[e0] * iq * inv[b * (2 * C) + C + h * CH + e0] * t;
    float x1 = (e1 < CH) ? row[e1] * iq * inv[b * (2 * C) + C + h * CH + e1] * t : -1e30f;
    float m = fmaxf(x0, x1);
    #pragma unroll
    for (int o = 16; o > 0; o >>= 1) m = fmaxf(m, __shfl_xor_sync(~0u, m, o));
    float ex0 = expf(x0 - m);
    float ex1 = (e1 < CH) ? expf(x1 - m) : 0.f;
    float s = ex0 + ex1;
    #pragma unroll
    for (int o = 16; o > 0; o >>= 1) s += __shfl_xor_sync(~0u, s, o);
    float r = 1.f / s;
    row[e0] = ex0 * r;
    if (e1 < CH) row[e1] = ex1 * r;
}

// ---------------- out[b, h*48+c, n] = sum_e attn[c,e] * v[b, 384+h*48+e, n] ----------------
__global__ __launch_bounds__(128) void av_gemm(const float* __restrict__ dw,
                                               const float* __restrict__ attn,
                                               float* __restrict__ outb)
{
    int b = blockIdx.z, h = blockIdx.y;
    int n = blockIdx.x * 128 + threadIdx.x;
    __shared__ float As[CH][CH];
    const float* am = attn + (size_t)(b * HEADS + h) * CH * CH;
    for (int i = threadIdx.x; i < CH * CH; i += 128) {
        int c = i / CH, e = i % CH;
        As[e][c] = am[c * CH + e];
    }
    __syncthreads();
    const float* V = dw + ((size_t)b * C3 + 2 * C + h * CH) * NPTS;
    float acc[CH];
    #pragma unroll
    for (int c = 0; c < CH; c++) acc[c] = 0.f;
    #pragma unroll 4
    for (int e = 0; e < CH; e++) {
        float vv = V[(size_t)e * NPTS + n];
        #pragma unroll
        for (int c4 = 0; c4 < CH; c4 += 4) {
            float4 a = *reinterpret_cast<const float4*>(&As[e][c4]);
            acc[c4 + 0] += a.x * vv; acc[c4 + 1] += a.y * vv;
            acc[c4 + 2] += a.z * vv; acc[c4 + 3] += a.w * vv;
        }
    }
    float* O = outb + ((size_t)b * C + h * CH) * NPTS + n;
    #pragma unroll
    for (int c = 0; c < CH; c++) O[(size_t)c * NPTS] = acc[c];
}

// ---------------- launch ----------------
extern "C" void kernel_launch(void* const* d_in, const int* in_sizes, int n_in,
                              void* d_out, int out_size)
{
    const float* x      = (const float*)d_in[0];
    const float* qkv_w  = (const float*)d_in[1];
    const float* qkv_b  = (const float*)d_in[2];
    const float* dw_w   = (const float*)d_in[3];
    const float* dw_b   = (const float*)d_in[4];
    const float* proj_w = (const float*)d_in[5];
    const float* proj_b = (const float*)d_in[6];
    const float* temp   = (const float*)d_in[7];
    float* out = (float*)d_out;

    float *qkv, *dwp, *obp, *invp, *atp;
    cudaGetSymbolAddress((void**)&qkv,  g_qkv);
    cudaGetSymbolAddress((void**)&dwp,  g_dw);
    cudaGetSymbolAddress((void**)&obp,  g_ob);
    cudaGetSymbolAddress((void**)&invp, g_inv);
    cudaGetSymbolAddress((void**)&atp,  g_at);

    // 1) qkv 1x1 conv via mma.sync (hi/lo bf16 split)
    gemm_mma<<<dim3(NPTS / BNg, C3 / BMg, B), 256>>>(x, qkv_w, qkv_b, qkv, C3);
    // 2) depthwise 3x3x3
    dwconv3<<<B * C3, 256>>>(qkv, dw_w, dw_b, dwp);
    // 3) inverse L2 norms for q/k rows
    rownorm<<<B * 2 * C, 256>>>(dwp, invp);
    // 4) q @ k^T (raw), n-split with atomics
    zerok<<<(B * HEADS * CH * CH + 255) / 256, 256>>>(atp, B * HEADS * CH * CH);
    qk_gemm<<<dim3(NSPLIT, HEADS, B), 256>>>(dwp, atp);
    // 5) scale + softmax
    softmaxk<<<(B * HEADS * CH + 7) / 8, 256>>>(atp, invp, temp);
    // 6) attn @ v
    av_gemm<<<dim3(NPTS / 128, HEADS, B), 128>>>(dwp, atp, obp);
    // 7) proj 1x1 conv via mma.sync
    gemm_mma<<<dim3(NPTS / BNg, C / BMg, B), 256>>>(obp, proj_w, proj_b, out, C);
}

// round 4
// speedup vs baseline: 1.6188x; 1.0827x over previous
#include <cuda_runtime.h>
#include <cuda_bf16.h>
#include <cstdint>

#define B 2
#define C 192
#define C3 576
#define SDIM 32
#define NPTS 32768           // 32^3
#define HEADS 4
#define CH 48
#define EPS 1e-12f

// ---------------- scratch (static device allocations) ----------------
__device__ float g_qkv[(size_t)B * C3 * NPTS];   // after 1x1 conv
__device__ float g_dw [(size_t)B * C3 * NPTS];   // after depthwise conv
__device__ float g_ob [(size_t)B * C  * NPTS];   // attention output (pre-proj)
__device__ float g_ssq[B * 2 * C];               // sum of squares for q/k rows
__device__ float g_at [B * HEADS * CH * CH];     // attention logits / probs
__device__ __nv_bfloat16 g_wh[C3 * C + C * C];   // pre-converted weights hi
__device__ __nv_bfloat16 g_wl[C3 * C + C * C];   // pre-converted weights lo

// ================= mma.sync helpers (sm_80-compatible, works on base sm_103) ======
__device__ __forceinline__ uint32_t smem_u32(const void* p) {
    uint32_t a;
    asm("{ .reg .u64 t; cvta.to.shared.u64 t, %1; cvt.u32.u64 %0, t; }" : "=r"(a) : "l"(p));
    return a;
}
__device__ __forceinline__ void ldsm4(uint32_t* r, uint32_t a) {
    asm volatile("ldmatrix.sync.aligned.m8n8.x4.shared.b16 {%0,%1,%2,%3}, [%4];"
                 : "=r"(r[0]), "=r"(r[1]), "=r"(r[2]), "=r"(r[3]) : "r"(a));
}
__device__ __forceinline__ void ldsm2t(uint32_t* r, uint32_t a) {
    asm volatile("ldmatrix.sync.aligned.m8n8.x2.trans.shared.b16 {%0,%1}, [%2];"
                 : "=r"(r[0]), "=r"(r[1]) : "r"(a));
}
__device__ __forceinline__ void mma_bf16(float* d, const uint32_t* a, const uint32_t* b) {
    asm volatile(
        "mma.sync.aligned.m16n8k16.row.col.f32.bf16.bf16.f32 "
        "{%0,%1,%2,%3}, {%4,%5,%6,%7}, {%8,%9}, {%0,%1,%2,%3};"
        : "+f"(d[0]), "+f"(d[1]), "+f"(d[2]), "+f"(d[3])
        : "r"(a[0]), "r"(a[1]), "r"(a[2]), "r"(a[3]), "r"(b[0]), "r"(b[1]));
}
__device__ __forceinline__ void cvt_hilo4(const float4 v, uint2& hi, uint2& lo) {
    __nv_bfloat162 h0 = __floats2bfloat162_rn(v.x, v.y);
    __nv_bfloat162 h1 = __floats2bfloat162_rn(v.z, v.w);
    float rx = v.x - __bfloat162float(h0.x);
    float ry = v.y - __bfloat162float(h0.y);
    float rz = v.z - __bfloat162float(h1.x);
    float rw = v.w - __bfloat162float(h1.y);
    __nv_bfloat162 l0 = __floats2bfloat162_rn(rx, ry);
    __nv_bfloat162 l1 = __floats2bfloat162_rn(rz, rw);
    hi.x = *reinterpret_cast<uint32_t*>(&h0); hi.y = *reinterpret_cast<uint32_t*>(&h1);
    lo.x = *reinterpret_cast<uint32_t*>(&l0); lo.y = *reinterpret_cast<uint32_t*>(&l1);
}

// ---------------- weight pre-conversion to bf16 hi/lo ----------------
__global__ void cvtW(const float* __restrict__ qkv_w, const float* __restrict__ proj_w,
                     __nv_bfloat16* __restrict__ wh, __nv_bfloat16* __restrict__ wl)
{
    int i = blockIdx.x * 256 + threadIdx.x;
    const int T0 = C3 * C, T1 = C3 * C + C * C;
    if (i >= T1) return;
    float v = (i < T0) ? qkv_w[i] : proj_w[i - T0];
    __nv_bfloat16 h = __float2bfloat16_rn(v);
    wh[i] = h;
    wl[i] = __float2bfloat16_rn(v - __bfloat162float(h));
}

// ---------------- tensor-core 1x1 conv via mma.sync ----------------
// Y[b,o,n] = sum_c W[o,c] X[b,c,n] + bias[o]
// A = W tile [BM=192 x BK=32] from pre-converted bf16 (pitch 40 halves)
// B = X tile [BK=32 x BN=128] converted inline (pitch 136 halves)
#define BMg 192
#define BNg 128
#define BKg 32
#define PA 40
#define PB 136

__global__ __launch_bounds__(512) void gemm_mma(
    const float* __restrict__ Xall,
    const __nv_bfloat16* __restrict__ WH, const __nv_bfloat16* __restrict__ WL,
    const float* __restrict__ bias, float* __restrict__ Yall, int O)
{
    __shared__ __align__(16) uint16_t sAhi[BMg * PA], sAlo[BMg * PA];
    __shared__ __align__(16) uint16_t sBhi[BKg * PB], sBlo[BKg * PB];

    const int tid = threadIdx.x, wid = tid >> 5, lane = tid & 31;
    const int n0 = blockIdx.x * BNg;
    const int o0 = blockIdx.y * BMg;
    const float* X = Xall + (size_t)blockIdx.z * C * NPTS;
    float*       Y = Yall + (size_t)blockIdx.z * O * NPTS;

    const int warp_m = (wid >> 2) * 48;   // 4 warps in M (48 rows each)
    const int warp_n = (wid & 3) * 32;    // 4 warps in N

    const uint32_t bAhi = smem_u32(sAhi), bAlo = smem_u32(sAlo);
    const uint32_t bBhi = smem_u32(sBhi), bBlo = smem_u32(sBlo);

    const uint32_t aOff = ((warp_m + (lane & 15)) * PA + (lane >> 4) * 8) * 2;
    const uint32_t bOff = ((lane & 15) * PB + warp_n) * 2;

    float acc[3][4][4] = {};

    for (int kc = 0; kc < C; kc += BKg) {
        // --- A tile: pre-converted bf16 W [192 x 32]
        #pragma unroll
        for (int q = 0; q < 3; q++) {
            int t = tid + q * 512;            // 1536 uint2 (4 halves each)
            int m = t >> 3, k4 = (t & 7) * 4;
            size_t gi = (size_t)(o0 + m) * C + kc + k4;
            *reinterpret_cast<uint2*>(&sAhi[m * PA + k4]) = *reinterpret_cast<const uint2*>(&WH[gi]);
            *reinterpret_cast<uint2*>(&sAlo[m * PA + k4]) = *reinterpret_cast<const uint2*>(&WL[gi]);
        }
        // --- B tile: X [32 x 128] converted inline
        #pragma unroll
        for (int q = 0; q < 2; q++) {
            int t = tid + q * 512;            // 1024 float4
            int c = t >> 5, n4 = (t & 31) * 4;
            float4 xv = *reinterpret_cast<const float4*>(&X[(size_t)(kc + c) * NPTS + n0 + n4]);
            uint2 hi, lo;
            cvt_hilo4(xv, hi, lo);
            *reinterpret_cast<uint2*>(&sBhi[c * PB + n4]) = hi;
            *reinterpret_cast<uint2*>(&sBlo[c * PB + n4]) = lo;
        }
        __syncthreads();

        #pragma unroll
        for (int ks = 0; ks < 2; ks++) {
            uint32_t Bhi[4][2], Blo[4][2];
            #pragma unroll
            for (int j = 0; j < 4; j++) {
                uint32_t off = bOff + j * 16 + ks * (16 * PB * 2);
                ldsm2t(Bhi[j], bBhi + off);
                ldsm2t(Blo[j], bBlo + off);
            }
            #pragma unroll
            for (int i = 0; i < 3; i++) {
                uint32_t Ahi[4], Alo[4];
                uint32_t off = aOff + i * (16 * PA * 2) + ks * 32;
                ldsm4(Ahi, bAhi + off);
                ldsm4(Alo, bAlo + off);
                #pragma unroll
                for (int j = 0; j < 4; j++) {
                    mma_bf16(acc[i][j], Ahi, Bhi[j]);
                    mma_bf16(acc[i][j], Ahi, Blo[j]);
                    mma_bf16(acc[i][j], Alo, Bhi[j]);
                }
            }
        }
        __syncthreads();
    }

    #pragma unroll
    for (int i = 0; i < 3; i++) {
        int m = o0 + warp_m + i * 16 + (lane >> 2);
        float bv0 = bias[m], bv1 = bias[m + 8];
        #pragma unroll
        for (int j = 0; j < 4; j++) {
            int n = n0 + warp_n + j * 8 + (lane & 3) * 2;
            float2 r0 = {acc[i][j][0] + bv0, acc[i][j][1] + bv0};
            float2 r1 = {acc[i][j][2] + bv1, acc[i][j][3] + bv1};
            *reinterpret_cast<float2*>(&Y[(size_t)m * NPTS + n]) = r0;
            *reinterpret_cast<float2*>(&Y[(size_t)(m + 8) * NPTS + n]) = r1;
        }
    }
}

// ---------------- depthwise 3x3x3 + fused q/k sum-of-squares ----------------
__global__ __launch_bounds__(256) void dwconv3(
    const float* __restrict__ in, const float* __restrict__ w,
    const float* __restrict__ bias, float* __restrict__ out,
    float* __restrict__ ssq)
{
    int bc = blockIdx.x;
    int b  = bc / C3;
    int c  = bc % C3;
    const float* vol  = in  + (size_t)bc * NPTS;
    float*       ovol = out + (size_t)bc * NPTS;

    float wr[27];
    #pragma unroll
    for (int i = 0; i < 27; i++) wr[i] = w[c * 27 + i];
    float bv = bias[c];

    __shared__ float P[3][34][36];        // padded rows -> 16B-aligned stencil reads
    __shared__ float sred[8];
    int tid = threadIdx.x;
    for (int i = tid; i < 3 * 34 * 36; i += 256) ((float*)P)[i] = 0.f;
    __syncthreads();
    {   // load plane 0 (one float4 per thread)
        int y = tid >> 3, x4 = (tid & 7) * 4;
        float4 v = *reinterpret_cast<const float4*>(&vol[y * 32 + x4]);
        P[0][1 + y][1 + x4 + 0] = v.x; P[0][1 + y][1 + x4 + 1] = v.y;
        P[0][1 + y][1 + x4 + 2] = v.z; P[0][1 + y][1 + x4 + 3] = v.w;
    }
    __syncthreads();

    int tx4 = (tid & 7) * 4;
    int ty  = tid >> 3;
    float qs = 0.f;                        // local sum of squares (q/k rows only)
    const bool need_ssq = (c < 2 * C);

    for (int z = 0; z < SDIM; z++) {
        int nb = (z + 1) % 3;
        if (z + 1 < SDIM) {
            int y = tid >> 3, x4 = (tid & 7) * 4;
            float4 v = *reinterpret_cast<const float4*>(&vol[(size_t)(z + 1) * 1024 + y * 32 + x4]);
            P[nb][1 + y][1 + x4 + 0] = v.x; P[nb][1 + y][1 + x4 + 1] = v.y;
            P[nb][1 + y][1 + x4 + 2] = v.z; P[nb][1 + y][1 + x4 + 3] = v.w;
        } else {
            for (int i = tid; i < 34 * 36; i += 256) ((float*)P[nb])[i] = 0.f;
        }
        __syncthreads();
        int pm = (z + 2) % 3;
        int pc = z % 3;
        float a0 = bv, a1 = bv, a2 = bv, a3 = bv;
        #pragma unroll
        for (int dz = 0; dz < 3; dz++) {
            int pi = (dz == 0) ? pm : (dz == 1) ? pc : nb;
            #pragma unroll
            for (int dy = 0; dy < 3; dy++) {
                const float* row = &P[pi][ty + dy][tx4];
                float4 rA = *reinterpret_cast<const float4*>(row);
                float2 rB = *reinterpret_cast<const float2*>(row + 4);
                float w0 = wr[dz * 9 + dy * 3 + 0];
                float w1 = wr[dz * 9 + dy * 3 + 1];
                float w2 = wr[dz * 9 + dy * 3 + 2];
                a0 += w0 * rA.x + w1 * rA.y + w2 * rA.z;
                a1 += w0 * rA.y + w1 * rA.z + w2 * rA.w;
                a2 += w0 * rA.z + w1 * rA.w + w2 * rB.x;
                a3 += w0 * rA.w + w1 * rB.x + w2 * rB.y;
            }
        }
        float4 o = {a0, a1, a2, a3};
        *reinterpret_cast<float4*>(&ovol[(size_t)z * 1024 + ty * 32 + tx4]) = o;
        if (need_ssq) qs += a0 * a0 + a1 * a1 + a2 * a2 + a3 * a3;
        __syncthreads();
    }

    if (need_ssq) {
        #pragma unroll
        for (int o = 16; o > 0; o >>= 1) qs += __shfl_xor_sync(~0u, qs, o);
        if ((tid & 31) == 0) sred[tid >> 5] = qs;
        __syncthreads();
        if (tid < 8) {
            float v = sred[tid];
            #pragma unroll
            for (int o = 4; o > 0; o >>= 1) v += __shfl_xor_sync(0xffu, v, o);
            if (tid == 0) ssq[b * 2 * C + c] = v;
        }
    }
}

__global__ void zerok(float* p, int n)
{
    int i = blockIdx.x * blockDim.x + threadIdx.x;
    if (i < n) p[i] = 0.f;
}

// ---------------- attn_raw[b,h,c,e] += sum_{n-slab} q[c,n]*k[e,n] ----------------
#define QKNT 32
#define NSPLIT 32
__global__ __launch_bounds__(256) void qk_gemm(const float* __restrict__ dw,
                                               float* __restrict__ attn)
{
    int b = blockIdx.z, h = blockIdx.y;
    int n0 = blockIdx.x * (NPTS / NSPLIT);
    const float* Q = dw + ((size_t)b * C3 + h * CH) * NPTS;
    const float* K = dw + ((size_t)b * C3 + C + h * CH) * NPTS;

    __shared__ float Qs[QKNT][49];
    __shared__ float Ks[QKNT][49];
    int tid = threadIdx.x;
    int tc = tid >> 4, te = tid & 15;
    float acc[3][3] = {};

    for (int nc = 0; nc < NPTS / NSPLIT; nc += QKNT) {
        int lane = tid & 31, wrp = tid >> 5;
        for (int cc = wrp; cc < CH; cc += 8) {
            Qs[lane][cc] = Q[(size_t)cc * NPTS + n0 + nc + lane];
            Ks[lane][cc] = K[(size_t)cc * NPTS + n0 + nc + lane];
        }
        __syncthreads();
        #pragma unroll
        for (int nn = 0; nn < QKNT; nn++) {
            float a0 = Qs[nn][tc * 3], a1 = Qs[nn][tc * 3 + 1], a2 = Qs[nn][tc * 3 + 2];
            float b0 = Ks[nn][te * 3], b1 = Ks[nn][te * 3 + 1], b2 = Ks[nn][te * 3 + 2];
            acc[0][0] += a0 * b0; acc[0][1] += a0 * b1; acc[0][2] += a0 * b2;
            acc[1][0] += a1 * b0; acc[1][1] += a1 * b1; acc[1][2] += a1 * b2;
            acc[2][0] += a2 * b0; acc[2][1] += a2 * b1; acc[2][2] += a2 * b2;
        }
        __syncthreads();
    }
    float* dst = attn + (size_t)(b * HEADS + h) * CH * CH;
    #pragma unroll
    for (int i = 0; i < 3; i++)
        #pragma unroll
        for (int j = 0; j < 3; j++)
            atomicAdd(&dst[(tc * 3 + i) * CH + te * 3 + j], acc[i][j]);
}

// ---------------- scale by 1/max(||.||,eps) + temperature, softmax over e ----------------
__global__ void softmaxk(float* __restrict__ attn, const float* __restrict__ ssq,
                         const float* __restrict__ temp)
{
    int gw = blockIdx.x * (blockDim.x / 32) + (threadIdx.x >> 5);
    if (gw >= B * HEADS * CH) return;
    int lane = threadIdx.x & 31;
    int c = gw % CH, bh = gw / CH, h = bh % HEADS, b = bh / HEADS;
    float* row = attn + (size_t)gw * CH;
    float iq = 1.f / fmaxf(sqrtf(ssq[b * 2 * C + h * CH + c]), EPS);
    float t  = temp[h];
    int e0 = lane, e1 = lane + 32;
    float ik0 = 1.f / fmaxf(sqrtf(ssq[b * 2 * C + C + h * CH + e0]), EPS);
    float x0 = row[e0] * iq * ik0 * t;
    float x1 = -1e30f;
    if (e1 < CH) {
        float ik1 = 1.f / fmaxf(sqrtf(ssq[b * 2 * C + C + h * CH + e1]), EPS);
        x1 = row[e1] * iq * ik1 * t;
    }
    float m = fmaxf(x0, x1);
    #pragma unroll
    for (int o = 16; o > 0; o >>= 1) m = fmaxf(m, __shfl_xor_sync(~0u, m, o));
    float ex0 = expf(x0 - m);
    float ex1 = (e1 < CH) ? expf(x1 - m) : 0.f;
    float s = ex0 + ex1;
    #pragma unroll
    for (int o = 16; o > 0; o >>= 1) s += __shfl_xor_sync(~0u, s, o);
    float r = 1.f / s;
    row[e0] = ex0 * r;
    if (e1 < CH) row[e1] = ex1 * r;
}

// ---------------- out[b, h*48+c, n] = sum_e attn[c,e] * v[b, 384+h*48+e, n] ----------------
__global__ __launch_bounds__(128) void av_gemm(const float* __restrict__ dw,
                                               const float* __restrict__ attn,
                                               float* __restrict__ outb)
{
    int b = blockIdx.z, h = blockIdx.y;
    int n = blockIdx.x * 128 + threadIdx.x;
    __shared__ float As[CH][CH];
    const float* am = attn + (size_t)(b * HEADS + h) * CH * CH;
    for (int i = threadIdx.x; i < CH * CH; i += 128) {
        int c = i / CH, e = i % CH;
        As[e][c] = am[c * CH + e];
    }
    __syncthreads();
    const float* V = dw + ((size_t)b * C3 + 2 * C + h * CH) * NPTS;
    float acc[CH];
    #pragma unroll
    for (int c = 0; c < CH; c++) acc[c] = 0.f;
    #pragma unroll 4
    for (int e = 0; e < CH; e++) {
        float vv = V[(size_t)e * NPTS + n];
        #pragma unroll
        for (int c4 = 0; c4 < CH; c4 += 4) {
            float4 a = *reinterpret_cast<const float4*>(&As[e][c4]);
            acc[c4 + 0] += a.x * vv; acc[c4 + 1] += a.y * vv;
            acc[c4 + 2] += a.z * vv; acc[c4 + 3] += a.w * vv;
        }
    }
    float* O = outb + ((size_t)b * C + h * CH) * NPTS + n;
    #pragma unroll
    for (int c = 0; c < CH; c++) O[(size_t)c * NPTS] = acc[c];
}

// ---------------- launch ----------------
extern "C" void kernel_launch(void* const* d_in, const int* in_sizes, int n_in,
                              void* d_out, int out_size)
{
    const float* x      = (const float*)d_in[0];
    const float* qkv_w  = (const float*)d_in[1];
    const float* qkv_b  = (const float*)d_in[2];
    const float* dw_w   = (const float*)d_in[3];
    const float* dw_b   = (const float*)d_in[4];
    const float* proj_w = (const float*)d_in[5];
    const float* proj_b = (const float*)d_in[6];
    const float* temp   = (const float*)d_in[7];
    float* out = (float*)d_out;

    float *qkv, *dwp, *obp, *ssqp, *atp;
    __nv_bfloat16 *whp, *wlp;
    cudaGetSymbolAddress((void**)&qkv,  g_qkv);
    cudaGetSymbolAddress((void**)&dwp,  g_dw);
    cudaGetSymbolAddress((void**)&obp,  g_ob);
    cudaGetSymbolAddress((void**)&ssqp, g_ssq);
    cudaGetSymbolAddress((void**)&atp,  g_at);
    cudaGetSymbolAddress((void**)&whp,  g_wh);
    cudaGetSymbolAddress((void**)&wlp,  g_wl);

    // 0) pre-convert weights to bf16 hi/lo
    cvtW<<<(C3 * C + C * C + 255) / 256, 256>>>(qkv_w, proj_w, whp, wlp);
    // 1) qkv 1x1 conv via mma.sync (hi/lo bf16 split)
    gemm_mma<<<dim3(NPTS / BNg, C3 / BMg, B), 512>>>(x, whp, wlp, qkv_b, qkv, C3);
    // 2) depthwise 3x3x3 (+ fused q/k sum-of-squares)
    dwconv3<<<B * C3, 256>>>(qkv, dw_w, dw_b, dwp, ssqp);
    // 3) q @ k^T (raw), n-split with atomics
    zerok<<<(B * HEADS * CH * CH + 255) / 256, 256>>>(atp, B * HEADS * CH * CH);
    qk_gemm<<<dim3(NSPLIT, HEADS, B), 256>>>(dwp, atp);
    // 4) scale + softmax (norms computed inline from ssq)
    softmaxk<<<(B * HEADS * CH + 7) / 8, 256>>>(atp, ssqp, temp);
    // 5) attn @ v
    av_gemm<<<dim3(NPTS / 128, HEADS, B), 128>>>(dwp, atp, obp);
    // 6) proj 1x1 conv via mma.sync
    gemm_mma<<<dim3(NPTS / BNg, C / BMg, B), 512>>>(obp, whp + C3 * C, wlp + C3 * C,
                                                    proj_b, out, C);
}

// round 5
// speedup vs baseline: 2.1379x; 1.3207x over previous
#include <cuda_runtime.h>
#include <cuda_fp16.h>
#include <cstdint>

#define B 2
#define C 192
#define C3 576
#define SDIM 32
#define NPTS 32768           // 32^3
#define HEADS 4
#define CH 48
#define EPS 1e-12f

// ---------------- scratch (static device allocations) ----------------
__device__ float g_qkv[(size_t)B * C3 * NPTS];   // after 1x1 conv
__device__ float g_dw [(size_t)B * C3 * NPTS];   // after depthwise conv
__device__ float g_ssq[B * 2 * C];               // sum of squares for q/k rows
__device__ float g_at [B * HEADS * CH * CH];     // attention logits / probs
__device__ __half g_wh [C3 * C];                 // qkv weights fp16
__device__ __half g_w2h[B * C * C];              // fused proj∘attn weights fp16 (per batch)

// ================= mma.sync helpers =================
__device__ __forceinline__ uint32_t smem_u32(const void* p) {
    uint32_t a;
    asm("{ .reg .u64 t; cvta.to.shared.u64 t, %1; cvt.u32.u64 %0, t; }" : "=r"(a) : "l"(p));
    return a;
}
__device__ __forceinline__ void ldsm4(uint32_t* r, uint32_t a) {
    asm volatile("ldmatrix.sync.aligned.m8n8.x4.shared.b16 {%0,%1,%2,%3}, [%4];"
                 : "=r"(r[0]), "=r"(r[1]), "=r"(r[2]), "=r"(r[3]) : "r"(a));
}
__device__ __forceinline__ void ldsm2t(uint32_t* r, uint32_t a) {
    asm volatile("ldmatrix.sync.aligned.m8n8.x2.trans.shared.b16 {%0,%1}, [%2];"
                 : "=r"(r[0]), "=r"(r[1]) : "r"(a));
}
__device__ __forceinline__ void mma_f16(float* d, const uint32_t* a, const uint32_t* b) {
    asm volatile(
        "mma.sync.aligned.m16n8k16.row.col.f32.f16.f16.f32 "
        "{%0,%1,%2,%3}, {%4,%5,%6,%7}, {%8,%9}, {%0,%1,%2,%3};"
        : "+f"(d[0]), "+f"(d[1]), "+f"(d[2]), "+f"(d[3])
        : "r"(a[0]), "r"(a[1]), "r"(a[2]), "r"(a[3]), "r"(b[0]), "r"(b[1]));
}
__device__ __forceinline__ uint2 cvt4h(const float4 v) {
    __half2 h0 = __floats2half2_rn(v.x, v.y);
    __half2 h1 = __floats2half2_rn(v.z, v.w);
    uint2 r;
    r.x = *reinterpret_cast<uint32_t*>(&h0);
    r.y = *reinterpret_cast<uint32_t*>(&h1);
    return r;
}

// ---------------- qkv weight fp16 conversion + attn buffer zeroing ----------------
__global__ void cvtW(const float* __restrict__ qkv_w, __half* __restrict__ wh,
                     float* __restrict__ attn)
{
    int i = blockIdx.x * 256 + threadIdx.x;
    const int T0 = C3 * C;                        // 110592
    const int T1 = T0 + B * HEADS * CH * CH;      // + 18432
    if (i < T0)       wh[i] = __float2half_rn(qkv_w[i]);
    else if (i < T1)  attn[i - T0] = 0.f;
}

// ---------------- 1x1 conv GEMM via fp16 mma.sync ----------------
// Y[b,o,n] = sum_c W[o,c] X[b,c,n] + bias[o]
// A = W tile [BM=192 x BK=32] fp16 (pitch 40), B = X tile [BK=32 x BN=128] (pitch 136)
#define BMg 192
#define BNg 128
#define BKg 32
#define PA 40
#define PB 136

__global__ __launch_bounds__(512) void gemm_mma(
    const float* __restrict__ Xall, size_t xbs,
    const __half* __restrict__ WH, size_t wbs,
    const float* __restrict__ bias, float* __restrict__ Yall, size_t ybs)
{
    __shared__ __align__(16) uint16_t sA[BMg * PA];
    __shared__ __align__(16) uint16_t sB[BKg * PB];

    const int tid = threadIdx.x, wid = tid >> 5, lane = tid & 31;
    const int n0 = blockIdx.x * BNg;
    const int o0 = blockIdx.y * BMg;
    const float*  X = Xall + (size_t)blockIdx.z * xbs;
    const __half* W = WH   + (size_t)blockIdx.z * wbs;
    float*        Y = Yall + (size_t)blockIdx.z * ybs;

    const int warp_m = (wid >> 2) * 48;
    const int warp_n = (wid & 3) * 32;

    const uint32_t bA = smem_u32(sA);
    const uint32_t bB = smem_u32(sB);
    const uint32_t aOff = ((warp_m + (lane & 15)) * PA + (lane >> 4) * 8) * 2;
    const uint32_t bOff = ((lane & 15) * PB + warp_n) * 2;

    float acc[3][4][4] = {};

    for (int kc = 0; kc < C; kc += BKg) {
        // A tile: fp16 W [192 x 32]
        #pragma unroll
        for (int q = 0; q < 3; q++) {
            int t = tid + q * 512;
            int m = t >> 3, k4 = (t & 7) * 4;
            *reinterpret_cast<uint2*>(&sA[m * PA + k4]) =
                *reinterpret_cast<const uint2*>(&W[(size_t)(o0 + m) * C + kc + k4]);
        }
        // B tile: X [32 x 128] fp32 -> fp16
        #pragma unroll
        for (int q = 0; q < 2; q++) {
            int t = tid + q * 512;
            int c = t >> 5, n4 = (t & 31) * 4;
            float4 xv = *reinterpret_cast<const float4*>(&X[(size_t)(kc + c) * NPTS + n0 + n4]);
            *reinterpret_cast<uint2*>(&sB[c * PB + n4]) = cvt4h(xv);
        }
        __syncthreads();

        #pragma unroll
        for (int ks = 0; ks < 2; ks++) {
            uint32_t Bf[4][2];
            #pragma unroll
            for (int j = 0; j < 4; j++)
                ldsm2t(Bf[j], bB + bOff + j * 16 + ks * (16 * PB * 2));
            #pragma unroll
            for (int i = 0; i < 3; i++) {
                uint32_t Af[4];
                ldsm4(Af, bA + aOff + i * (16 * PA * 2) + ks * 32);
                #pragma unroll
                for (int j = 0; j < 4; j++)
                    mma_f16(acc[i][j], Af, Bf[j]);
            }
        }
        __syncthreads();
    }

    #pragma unroll
    for (int i = 0; i < 3; i++) {
        int m = o0 + warp_m + i * 16 + (lane >> 2);
        float bv0 = bias[m], bv1 = bias[m + 8];
        #pragma unroll
        for (int j = 0; j < 4; j++) {
            int n = n0 + warp_n + j * 8 + (lane & 3) * 2;
            float2 r0 = {acc[i][j][0] + bv0, acc[i][j][1] + bv0};
            float2 r1 = {acc[i][j][2] + bv1, acc[i][j][3] + bv1};
            *reinterpret_cast<float2*>(&Y[(size_t)m * NPTS + n]) = r0;
            *reinterpret_cast<float2*>(&Y[(size_t)(m + 8) * NPTS + n]) = r1;
        }
    }
}

// ---------------- depthwise 3x3x3 + fused q/k sum-of-squares ----------------
__global__ __launch_bounds__(256) void dwconv3(
    const float* __restrict__ in, const float* __restrict__ w,
    const float* __restrict__ bias, float* __restrict__ out,
    float* __restrict__ ssq)
{
    int bc = blockIdx.x;
    int b  = bc / C3;
    int c  = bc % C3;
    const float* vol  = in  + (size_t)bc * NPTS;
    float*       ovol = out + (size_t)bc * NPTS;

    float wr[27];
    #pragma unroll
    for (int i = 0; i < 27; i++) wr[i] = w[c * 27 + i];
    float bv = bias[c];

    __shared__ float P[3][34][36];
    __shared__ float sred[8];
    int tid = threadIdx.x;
    for (int i = tid; i < 3 * 34 * 36; i += 256) ((float*)P)[i] = 0.f;
    __syncthreads();
    {
        int y = tid >> 3, x4 = (tid & 7) * 4;
        float4 v = *reinterpret_cast<const float4*>(&vol[y * 32 + x4]);
        P[0][1 + y][1 + x4 + 0] = v.x; P[0][1 + y][1 + x4 + 1] = v.y;
        P[0][1 + y][1 + x4 + 2] = v.z; P[0][1 + y][1 + x4 + 3] = v.w;
    }
    __syncthreads();

    int tx4 = (tid & 7) * 4;
    int ty  = tid >> 3;
    float qs = 0.f;
    const bool need_ssq = (c < 2 * C);

    for (int z = 0; z < SDIM; z++) {
        int nb = (z + 1) % 3;
        if (z + 1 < SDIM) {
            int y = tid >> 3, x4 = (tid & 7) * 4;
            float4 v = *reinterpret_cast<const float4*>(&vol[(size_t)(z + 1) * 1024 + y * 32 + x4]);
            P[nb][1 + y][1 + x4 + 0] = v.x; P[nb][1 + y][1 + x4 + 1] = v.y;
            P[nb][1 + y][1 + x4 + 2] = v.z; P[nb][1 + y][1 + x4 + 3] = v.w;
        } else {
            for (int i = tid; i < 34 * 36; i += 256) ((float*)P[nb])[i] = 0.f;
        }
        __syncthreads();
        int pm = (z + 2) % 3;
        int pc = z % 3;
        float a0 = bv, a1 = bv, a2 = bv, a3 = bv;
        #pragma unroll
        for (int dz = 0; dz < 3; dz++) {
            int pi = (dz == 0) ? pm : (dz == 1) ? pc : nb;
            #pragma unroll
            for (int dy = 0; dy < 3; dy++) {
                const float* row = &P[pi][ty + dy][tx4];
                float4 rA = *reinterpret_cast<const float4*>(row);
                float2 rB = *reinterpret_cast<const float2*>(row + 4);
                float w0 = wr[dz * 9 + dy * 3 + 0];
                float w1 = wr[dz * 9 + dy * 3 + 1];
                float w2 = wr[dz * 9 + dy * 3 + 2];
                a0 += w0 * rA.x + w1 * rA.y + w2 * rA.z;
                a1 += w0 * rA.y + w1 * rA.z + w2 * rA.w;
                a2 += w0 * rA.z + w1 * rA.w + w2 * rB.x;
                a3 += w0 * rA.w + w1 * rB.x + w2 * rB.y;
            }
        }
        float4 o = {a0, a1, a2, a3};
        *reinterpret_cast<float4*>(&ovol[(size_t)z * 1024 + ty * 32 + tx4]) = o;
        if (need_ssq) qs += a0 * a0 + a1 * a1 + a2 * a2 + a3 * a3;
        __syncthreads();
    }

    if (need_ssq) {
        #pragma unroll
        for (int o = 16; o > 0; o >>= 1) qs += __shfl_xor_sync(~0u, qs, o);
        if ((tid & 31) == 0) sred[tid >> 5] = qs;
        __syncthreads();
        if (tid < 8) {
            float v = sred[tid];
            #pragma unroll
            for (int o = 4; o > 0; o >>= 1) v += __shfl_xor_sync(0xffu, v, o);
            if (tid == 0) ssq[b * 2 * C + c] = v;
        }
    }
}

// ---------------- attn_raw[b,h,c,e] += sum_{n-slab} q[c,n]*k[e,n] ----------------
#define QKNT 32
#define NSPLIT 32
__global__ __launch_bounds__(256) void qk_gemm(const float* __restrict__ dw,
                                               float* __restrict__ attn)
{
    int b = blockIdx.z, h = blockIdx.y;
    int n0 = blockIdx.x * (NPTS / NSPLIT);
    const float* Q = dw + ((size_t)b * C3 + h * CH) * NPTS;
    const float* K = dw + ((size_t)b * C3 + C + h * CH) * NPTS;

    __shared__ float Qs[QKNT][49];
    __shared__ float Ks[QKNT][49];
    int tid = threadIdx.x;
    int tc = tid >> 4, te = tid & 15;
    float acc[3][3] = {};

    for (int nc = 0; nc < NPTS / NSPLIT; nc += QKNT) {
        int lane = tid & 31, wrp = tid >> 5;
        for (int cc = wrp; cc < CH; cc += 8) {
            Qs[lane][cc] = Q[(size_t)cc * NPTS + n0 + nc + lane];
            Ks[lane][cc] = K[(size_t)cc * NPTS + n0 + nc + lane];
        }
        __syncthreads();
        #pragma unroll
        for (int nn = 0; nn < QKNT; nn++) {
            float a0 = Qs[nn][tc * 3], a1 = Qs[nn][tc * 3 + 1], a2 = Qs[nn][tc * 3 + 2];
            float b0 = Ks[nn][te * 3], b1 = Ks[nn][te * 3 + 1], b2 = Ks[nn][te * 3 + 2];
            acc[0][0] += a0 * b0; acc[0][1] += a0 * b1; acc[0][2] += a0 * b2;
            acc[1][0] += a1 * b0; acc[1][1] += a1 * b1; acc[1][2] += a1 * b2;
            acc[2][0] += a2 * b0; acc[2][1] += a2 * b1; acc[2][2] += a2 * b2;
        }
        __syncthreads();
    }
    float* dst = attn + (size_t)(b * HEADS + h) * CH * CH;
    #pragma unroll
    for (int i = 0; i < 3; i++)
        #pragma unroll
        for (int j = 0; j < 3; j++)
            atomicAdd(&dst[(tc * 3 + i) * CH + te * 3 + j], acc[i][j]);
}

// ---------------- scale by 1/max(||.||,eps) + temperature, softmax over e ----------------
__global__ void softmaxk(float* __restrict__ attn, const float* __restrict__ ssq,
                         const float* __restrict__ temp)
{
    int gw = blockIdx.x * (blockDim.x / 32) + (threadIdx.x >> 5);
    if (gw >= B * HEADS * CH) return;
    int lane = threadIdx.x & 31;
    int c = gw % CH, bh = gw / CH, h = bh % HEADS, b = bh / HEADS;
    float* row = attn + (size_t)gw * CH;
    float iq = 1.f / fmaxf(sqrtf(ssq[b * 2 * C + h * CH + c]), EPS);
    float t  = temp[h];
    int e0 = lane, e1 = lane + 32;
    float ik0 = 1.f / fmaxf(sqrtf(ssq[b * 2 * C + C + h * CH + e0]), EPS);
    float x0 = row[e0] * iq * ik0 * t;
    float x1 = -1e30f;
    if (e1 < CH) {
        float ik1 = 1.f / fmaxf(sqrtf(ssq[b * 2 * C + C + h * CH + e1]), EPS);
        x1 = row[e1] * iq * ik1 * t;
    }
    float m = fmaxf(x0, x1);
    #pragma unroll
    for (int o = 16; o > 0; o >>= 1) m = fmaxf(m, __shfl_xor_sync(~0u, m, o));
    float ex0 = expf(x0 - m);
    float ex1 = (e1 < CH) ? expf(x1 - m) : 0.f;
    float s = ex0 + ex1;
    #pragma unroll
    for (int o = 16; o > 0; o >>= 1) s += __shfl_xor_sync(~0u, s, o);
    float r = 1.f / s;
    row[e0] = ex0 * r;
    if (e1 < CH) row[e1] = ex1 * r;
}

// ---------------- fuse proj weights with attention: W2[b][o][h*48+e] ----------------
//   = sum_c proj[o, h*48+c] * attn[b,h][c][e]      (8 blocks = (b,h); 192 threads = o)
__global__ __launch_bounds__(192) void fuseW(const float* __restrict__ proj_w,
                                             const float* __restrict__ attn,
                                             __half* __restrict__ w2)
{
    int bh = blockIdx.x;
    int h = bh % HEADS, b = bh / HEADS;
    __shared__ float At[CH][CH];          // At[c][e]
    const float* am = attn + (size_t)bh * CH * CH;
    for (int i = threadIdx.x; i < CH * CH; i += 192)
        At[i / CH][i % CH] = am[i];
    __syncthreads();

    int o = threadIdx.x;
    float pr[CH];
    #pragma unroll
    for (int c = 0; c < CH; c++) pr[c] = proj_w[(size_t)o * C + h * CH + c];

    __half* dst = w2 + (size_t)b * C * C + (size_t)o * C + h * CH;
    #pragma unroll 4
    for (int e = 0; e < CH; e++) {
        float acc = 0.f;
        #pragma unroll
        for (int c = 0; c < CH; c++) acc += pr[c] * At[c][e];
        dst[e] = __float2half_rn(acc);
    }
}

// ---------------- launch ----------------
extern "C" void kernel_launch(void* const* d_in, const int* in_sizes, int n_in,
                              void* d_out, int out_size)
{
    const float* x      = (const float*)d_in[0];
    const float* qkv_w  = (const float*)d_in[1];
    const float* qkv_b  = (const float*)d_in[2];
    const float* dw_w   = (const float*)d_in[3];
    const float* dw_b   = (const float*)d_in[4];
    const float* proj_w = (const float*)d_in[5];
    const float* proj_b = (const float*)d_in[6];
    const float* temp   = (const float*)d_in[7];
    float* out = (float*)d_out;

    float *qkv, *dwp, *ssqp, *atp;
    __half *whp, *w2p;
    cudaGetSymbolAddress((void**)&qkv,  g_qkv);
    cudaGetSymbolAddress((void**)&dwp,  g_dw);
    cudaGetSymbolAddress((void**)&ssqp, g_ssq);
    cudaGetSymbolAddress((void**)&atp,  g_at);
    cudaGetSymbolAddress((void**)&whp,  g_wh);
    cudaGetSymbolAddress((void**)&w2p,  g_w2h);

    // 0) qkv weights -> fp16, zero attn accumulator
    cvtW<<<(C3 * C + B * HEADS * CH * CH + 255) / 256, 256>>>(qkv_w, whp, atp);
    // 1) qkv 1x1 conv (fp16 tensor core)
    gemm_mma<<<dim3(NPTS / BNg, C3 / BMg, B), 512>>>(
        x, (size_t)C * NPTS, whp, 0, qkv_b, qkv, (size_t)C3 * NPTS);
    // 2) depthwise 3x3x3 (+ fused q/k sum-of-squares)
    dwconv3<<<B * C3, 256>>>(qkv, dw_w, dw_b, dwp, ssqp);
    // 3) q @ k^T (raw), n-split with atomics
    qk_gemm<<<dim3(NSPLIT, HEADS, B), 256>>>(dwp, atp);
    // 4) scale + softmax
    softmaxk<<<(B * HEADS * CH + 7) / 8, 256>>>(atp, ssqp, temp);
    // 5) fuse proj with attention -> per-batch fp16 weights
    fuseW<<<B * HEADS, 192>>>(proj_w, atp, w2p);
    // 6) fused (proj∘attn) @ v  -> final output
    gemm_mma<<<dim3(NPTS / BNg, 1, B), 512>>>(
        dwp + (size_t)2 * C * NPTS, (size_t)C3 * NPTS,
        w2p, (size_t)C * C, proj_b, out, (size_t)C * NPTS);
}

// round 6
// speedup vs baseline: 2.9684x; 1.3884x over previous
#include <cuda_runtime.h>
#include <cuda_fp16.h>
#include <cstdint>

#define B 2
#define C 192
#define C3 576
#define SDIM 32
#define NPTS 32768           // 32^3
#define HEADS 4
#define CH 48
#define EPS 1e-12f

// ---------------- scratch (static device allocations) ----------------
__device__ float  g_qkv[(size_t)B * C3 * NPTS];      // after 1x1 conv (fp32)
__device__ __half g_qkh[(size_t)B * 2 * C * NPTS];   // q,k after dwconv, fp16 hi
__device__ __half g_qkl[(size_t)B * 2 * C * NPTS];   // q,k after dwconv, fp16 lo (residual)
__device__ __half g_vh [(size_t)B * C * NPTS];       // v after dwconv, fp16
__device__ float  g_ssq[B * 2 * C];                  // sum of squares for q/k rows
__device__ float  g_at [B * HEADS * CH * CH];        // attention logits / probs
__device__ __half g_wh [C3 * C];                     // qkv weights fp16
__device__ __half g_w2h[B * C * C];                  // fused proj∘attn weights fp16

// ================= mma.sync helpers =================
__device__ __forceinline__ uint32_t smem_u32(const void* p) {
    uint32_t a;
    asm("{ .reg .u64 t; cvta.to.shared.u64 t, %1; cvt.u32.u64 %0, t; }" : "=r"(a) : "l"(p));
    return a;
}
__device__ __forceinline__ void ldsm4(uint32_t* r, uint32_t a) {
    asm volatile("ldmatrix.sync.aligned.m8n8.x4.shared.b16 {%0,%1,%2,%3}, [%4];"
                 : "=r"(r[0]), "=r"(r[1]), "=r"(r[2]), "=r"(r[3]) : "r"(a));
}
__device__ __forceinline__ void ldsm2(uint32_t* r, uint32_t a) {
    asm volatile("ldmatrix.sync.aligned.m8n8.x2.shared.b16 {%0,%1}, [%2];"
                 : "=r"(r[0]), "=r"(r[1]) : "r"(a));
}
__device__ __forceinline__ void ldsm2t(uint32_t* r, uint32_t a) {
    asm volatile("ldmatrix.sync.aligned.m8n8.x2.trans.shared.b16 {%0,%1}, [%2];"
                 : "=r"(r[0]), "=r"(r[1]) : "r"(a));
}
__device__ __forceinline__ void mma_f16(float* d, const uint32_t* a, const uint32_t* b) {
    asm volatile(
        "mma.sync.aligned.m16n8k16.row.col.f32.f16.f16.f32 "
        "{%0,%1,%2,%3}, {%4,%5,%6,%7}, {%8,%9}, {%0,%1,%2,%3};"
        : "+f"(d[0]), "+f"(d[1]), "+f"(d[2]), "+f"(d[3])
        : "r"(a[0]), "r"(a[1]), "r"(a[2]), "r"(a[3]), "r"(b[0]), "r"(b[1]));
}
__device__ __forceinline__ uint2 cvt4h(const float4 v) {
    __half2 h0 = __floats2half2_rn(v.x, v.y);
    __half2 h1 = __floats2half2_rn(v.z, v.w);
    uint2 r;
    r.x = *reinterpret_cast<uint32_t*>(&h0);
    r.y = *reinterpret_cast<uint32_t*>(&h1);
    return r;
}
#define CP_ASYNC16(dst, src) \
    asm volatile("cp.async.ca.shared.global [%0], [%1], 16;" :: "r"(dst), "l"(src))
#define CP_COMMIT() asm volatile("cp.async.commit_group;")

// ---------------- qkv weight fp16 conversion + attn buffer zeroing ----------------
__global__ void cvtW(const float* __restrict__ qkv_w, __half* __restrict__ wh,
                     float* __restrict__ attn)
{
    int i = blockIdx.x * 256 + threadIdx.x;
    const int T0 = C3 * C;
    const int T1 = T0 + B * HEADS * CH * CH;
    if (i < T0)       wh[i] = __float2half_rn(qkv_w[i]);
    else if (i < T1)  attn[i - T0] = 0.f;
}

// ---------------- 1x1 conv GEMM via fp16 mma.sync ----------------
#define BMg 192
#define BNg 128
#define BKg 32
#define PA 40
#define PB 136

template<int XHALF>
__global__ __launch_bounds__(512) void gemm_mma(
    const void* __restrict__ Xall, size_t xbs,
    const __half* __restrict__ WH, size_t wbs,
    const float* __restrict__ bias, float* __restrict__ Yall, size_t ybs)
{
    __shared__ __align__(16) uint16_t sA[BMg * PA];
    __shared__ __align__(16) uint16_t sB[BKg * PB];

    const int tid = threadIdx.x, wid = tid >> 5, lane = tid & 31;
    const int n0 = blockIdx.x * BNg;
    const int o0 = blockIdx.y * BMg;
    const __half* W = WH + (size_t)blockIdx.z * wbs;
    float*        Y = Yall + (size_t)blockIdx.z * ybs;

    const int warp_m = (wid >> 2) * 48;
    const int warp_n = (wid & 3) * 32;

    const uint32_t bA = smem_u32(sA);
    const uint32_t bB = smem_u32(sB);
    const uint32_t aOff = ((warp_m + (lane & 15)) * PA + (lane >> 4) * 8) * 2;
    const uint32_t bOff = ((lane & 15) * PB + warp_n) * 2;

    float acc[3][4][4] = {};

    for (int kc = 0; kc < C; kc += BKg) {
        #pragma unroll
        for (int q = 0; q < 3; q++) {
            int t = tid + q * 512;
            int m = t >> 3, k4 = (t & 7) * 4;
            *reinterpret_cast<uint2*>(&sA[m * PA + k4]) =
                *reinterpret_cast<const uint2*>(&W[(size_t)(o0 + m) * C + kc + k4]);
        }
        if (XHALF) {
            const __half* X = (const __half*)Xall + (size_t)blockIdx.z * xbs;
            #pragma unroll
            for (int q = 0; q < 2; q++) {
                int t = tid + q * 512;
                int c = t >> 7, n4 = (t & 127) * 4;   // 32 rows x (128 halfs / 4)
                *reinterpret_cast<uint2*>(&sB[(c * 4 + (n4 >> 7)) * PB + (n4 & 127)]) =
                    *reinterpret_cast<const uint2*>(
                        &X[(size_t)(kc + c * 4 + (n4 >> 7)) * NPTS + n0 + (n4 & 127)]);
            }
        } else {
            const float* X = (const float*)Xall + (size_t)blockIdx.z * xbs;
            #pragma unroll
            for (int q = 0; q < 2; q++) {
                int t = tid + q * 512;
                int c = t >> 5, n4 = (t & 31) * 4;
                float4 xv = *reinterpret_cast<const float4*>(&X[(size_t)(kc + c) * NPTS + n0 + n4]);
                *reinterpret_cast<uint2*>(&sB[c * PB + n4]) = cvt4h(xv);
            }
        }
        __syncthreads();

        #pragma unroll
        for (int ks = 0; ks < 2; ks++) {
            uint32_t Bf[4][2];
            #pragma unroll
            for (int j = 0; j < 4; j++)
                ldsm2t(Bf[j], bB + bOff + j * 16 + ks * (16 * PB * 2));
            #pragma unroll
            for (int i = 0; i < 3; i++) {
                uint32_t Af[4];
                ldsm4(Af, bA + aOff + i * (16 * PA * 2) + ks * 32);
                #pragma unroll
                for (int j = 0; j < 4; j++)
                    mma_f16(acc[i][j], Af, Bf[j]);
            }
        }
        __syncthreads();
    }

    #pragma unroll
    for (int i = 0; i < 3; i++) {
        int m = o0 + warp_m + i * 16 + (lane >> 2);
        float bv0 = bias[m], bv1 = bias[m + 8];
        #pragma unroll
        for (int j = 0; j < 4; j++) {
            int n = n0 + warp_n + j * 8 + (lane & 3) * 2;
            float2 r0 = {acc[i][j][0] + bv0, acc[i][j][1] + bv0};
            float2 r1 = {acc[i][j][2] + bv1, acc[i][j][3] + bv1};
            *reinterpret_cast<float2*>(&Y[(size_t)m * NPTS + n]) = r0;
            *reinterpret_cast<float2*>(&Y[(size_t)(m + 8) * NPTS + n]) = r1;
        }
    }
}

// ---------------- depthwise 3x3x3 -> fp16 hi/lo q,k + fp16 v + fused ssq ----------------
__global__ __launch_bounds__(256) void dwconv3(
    const float* __restrict__ in, const float* __restrict__ w,
    const float* __restrict__ bias,
    __half* __restrict__ qkh, __half* __restrict__ qkl, __half* __restrict__ vh,
    float* __restrict__ ssq)
{
    int bc = blockIdx.x;
    int b  = bc / C3;
    int c  = bc % C3;
    const float* vol = in + (size_t)bc * NPTS;

    float wr[27];
    #pragma unroll
    for (int i = 0; i < 27; i++) wr[i] = w[c * 27 + i];
    float bv = bias[c];

    __shared__ float P[3][34][36];
    __shared__ float sred[8];
    int tid = threadIdx.x;
    for (int i = tid; i < 3 * 34 * 36; i += 256) ((float*)P)[i] = 0.f;
    __syncthreads();
    {
        int y = tid >> 3, x4 = (tid & 7) * 4;
        float4 v = *reinterpret_cast<const float4*>(&vol[y * 32 + x4]);
        P[0][1 + y][1 + x4 + 0] = v.x; P[0][1 + y][1 + x4 + 1] = v.y;
        P[0][1 + y][1 + x4 + 2] = v.z; P[0][1 + y][1 + x4 + 3] = v.w;
    }
    __syncthreads();

    int tx4 = (tid & 7) * 4;
    int ty  = tid >> 3;
    float qs = 0.f;
    const bool is_qk = (c < 2 * C);
    __half* qkhp = qkh + ((size_t)b * 2 * C + c) * NPTS;
    __half* qklp = qkl + ((size_t)b * 2 * C + c) * NPTS;
    __half* vhp  = vh  + ((size_t)b * C + (c - 2 * C)) * NPTS;

    for (int z = 0; z < SDIM; z++) {
        int nb = (z + 1) % 3;
        if (z + 1 < SDIM) {
            int y = tid >> 3, x4 = (tid & 7) * 4;
            float4 v = *reinterpret_cast<const float4*>(&vol[(size_t)(z + 1) * 1024 + y * 32 + x4]);
            P[nb][1 + y][1 + x4 + 0] = v.x; P[nb][1 + y][1 + x4 + 1] = v.y;
            P[nb][1 + y][1 + x4 + 2] = v.z; P[nb][1 + y][1 + x4 + 3] = v.w;
        } else {
            for (int i = tid; i < 34 * 36; i += 256) ((float*)P[nb])[i] = 0.f;
        }
        __syncthreads();
        int pm = (z + 2) % 3;
        int pc = z % 3;
        float a0 = bv, a1 = bv, a2 = bv, a3 = bv;
        #pragma unroll
        for (int dz = 0; dz < 3; dz++) {
            int pi = (dz == 0) ? pm : (dz == 1) ? pc : nb;
            #pragma unroll
            for (int dy = 0; dy < 3; dy++) {
                const float* row = &P[pi][ty + dy][tx4];
                float4 rA = *reinterpret_cast<const float4*>(row);
                float2 rB = *reinterpret_cast<const float2*>(row + 4);
                float w0 = wr[dz * 9 + dy * 3 + 0];
                float w1 = wr[dz * 9 + dy * 3 + 1];
                float w2 = wr[dz * 9 + dy * 3 + 2];
                a0 += w0 * rA.x + w1 * rA.y + w2 * rA.z;
                a1 += w0 * rA.y + w1 * rA.z + w2 * rA.w;
                a2 += w0 * rA.z + w1 * rA.w + w2 * rB.x;
                a3 += w0 * rA.w + w1 * rB.x + w2 * rB.y;
            }
        }
        size_t off = (size_t)z * 1024 + ty * 32 + tx4;
        __half2 h0 = __floats2half2_rn(a0, a1);
        __half2 h1 = __floats2half2_rn(a2, a3);
        if (is_qk) {
            uint2 hv = {*reinterpret_cast<uint32_t*>(&h0), *reinterpret_cast<uint32_t*>(&h1)};
            *reinterpret_cast<uint2*>(&qkhp[off]) = hv;
            __half2 l0 = __floats2half2_rn(a0 - __half2float(h0.x), a1 - __half2float(h0.y));
            __half2 l1 = __floats2half2_rn(a2 - __half2float(h1.x), a3 - __half2float(h1.y));
            uint2 lv = {*reinterpret_cast<uint32_t*>(&l0), *reinterpret_cast<uint32_t*>(&l1)};
            *reinterpret_cast<uint2*>(&qklp[off]) = lv;
            qs += a0 * a0 + a1 * a1 + a2 * a2 + a3 * a3;
        } else {
            uint2 hv = {*reinterpret_cast<uint32_t*>(&h0), *reinterpret_cast<uint32_t*>(&h1)};
            *reinterpret_cast<uint2*>(&vhp[off]) = hv;
        }
        __syncthreads();
    }

    if (is_qk) {
        #pragma unroll
        for (int o = 16; o > 0; o >>= 1) qs += __shfl_xor_sync(~0u, qs, o);
        if ((tid & 31) == 0) sred[tid >> 5] = qs;
        __syncthreads();
        if (tid < 8) {
            float v = sred[tid];
            #pragma unroll
            for (int o = 4; o > 0; o >>= 1) v += __shfl_xor_sync(0xffu, v, o);
            if (tid == 0) ssq[b * 2 * C + c] = v;
        }
    }
}

// ---------------- q @ k^T via fp16 hi/lo mma.sync ----------------
// attn[b,h,c,e] += sum_n q[c,n]*k[e,n]; A = Q [48 x k], B = K [48 x k] (n8k16 via ldsm)
#define QKC 128                      // k-chunk per stage
#define QKP 136                      // smem pitch in halfs
#define QK_ARR (48 * QKP * 2)        // bytes per array (13056)
#define QK_STAGE (4 * QK_ARR)        // Qhi,Qlo,Khi,Klo (52224)
#define QK_NSPL 16
#define QK_SLAB (NPTS / QK_NSPL)     // 2048
#define QK_SMEM (2 * QK_STAGE + 48 * 49 * 4)

__global__ __launch_bounds__(256) void qk_mma(
    const __half* __restrict__ qkh, const __half* __restrict__ qkl,
    float* __restrict__ attn)
{
    extern __shared__ char smem[];
    float* sAcc = reinterpret_cast<float*>(smem + 2 * QK_STAGE);
    const int tid = threadIdx.x, wid = tid >> 5, lane = tid & 31;
    const int b = blockIdx.z, h = blockIdx.y;
    const int n0 = blockIdx.x * QK_SLAB;

    const __half* srcs[4] = {
        qkh + ((size_t)b * 2 * C + h * CH) * NPTS,        // Q hi
        qkl + ((size_t)b * 2 * C + h * CH) * NPTS,        // Q lo
        qkh + ((size_t)b * 2 * C + C + h * CH) * NPTS,    // K hi
        qkl + ((size_t)b * 2 * C + C + h * CH) * NPTS     // K lo
    };
    const uint32_t sbase = smem_u32(smem);

    for (int i = tid; i < 48 * 49; i += 256) sAcc[i] = 0.f;

    // per-thread load slots: 12 x 16B per stage
    int la[12], lr[12], lc[12];
    #pragma unroll
    for (int q = 0; q < 12; q++) {
        int idx = tid + q * 256;         // 0..3071
        la[q] = idx / 768;               // array
        int rem = idx % 768;
        lr[q] = rem / 16;                // row 0..47
        lc[q] = (rem % 16) * 8;          // col in halfs
    }

    const int NCH = QK_SLAB / QKC;       // 16
    // prologue: load chunk 0 into stage 0
    #pragma unroll
    for (int q = 0; q < 12; q++) {
        uint32_t dst = sbase + la[q] * QK_ARR + (lr[q] * QKP + lc[q]) * 2;
        CP_ASYNC16(dst, srcs[la[q]] + (size_t)lr[q] * NPTS + n0 + lc[q]);
    }
    CP_COMMIT();

    float acc[3][6][4] = {};
    const int k0 = wid * 16;

    for (int ch = 0; ch < NCH; ch++) {
        if (ch + 1 < NCH) {
            uint32_t st = ((ch + 1) & 1) * QK_STAGE;
            int nb = n0 + (ch + 1) * QKC;
            #pragma unroll
            for (int q = 0; q < 12; q++) {
                uint32_t dst = sbase + st + la[q] * QK_ARR + (lr[q] * QKP + lc[q]) * 2;
                CP_ASYNC16(dst, srcs[la[q]] + (size_t)lr[q] * NPTS + nb + lc[q]);
            }
            CP_COMMIT();
            asm volatile("cp.async.wait_group 1;");
        } else {
            asm volatile("cp.async.wait_group 0;");
        }
        __syncthreads();

        const uint32_t st = sbase + (ch & 1) * QK_STAGE;
        uint32_t Ahi[3][4], Alo[3][4], Bhi[6][2], Blo[6][2];
        #pragma unroll
        for (int i = 0; i < 3; i++) {
            uint32_t off = ((i * 16 + (lane & 15)) * QKP + k0 + (lane >> 4) * 8) * 2;
            ldsm4(Ahi[i], st + off);
            ldsm4(Alo[i], st + QK_ARR + off);
        }
        #pragma unroll
        for (int j = 0; j < 6; j++) {
            uint32_t off = ((j * 8 + (lane & 7)) * QKP + k0 + ((lane >> 3) & 1) * 8) * 2;
            ldsm2(Bhi[j], st + 2 * QK_ARR + off);
            ldsm2(Blo[j], st + 3 * QK_ARR + off);
        }
        #pragma unroll
        for (int i = 0; i < 3; i++)
            #pragma unroll
            for (int j = 0; j < 6; j++) {
                mma_f16(acc[i][j], Ahi[i], Bhi[j]);
                mma_f16(acc[i][j], Ahi[i], Blo[j]);
                mma_f16(acc[i][j], Alo[i], Bhi[j]);
            }
        __syncthreads();
    }

    // reduce 8 warps into sAcc
    #pragma unroll
    for (int i = 0; i < 3; i++) {
        int m = i * 16 + (lane >> 2);
        #pragma unroll
        for (int j = 0; j < 6; j++) {
            int n = j * 8 + (lane & 3) * 2;
            atomicAdd(&sAcc[m * 49 + n],           acc[i][j][0]);
            atomicAdd(&sAcc[m * 49 + n + 1],       acc[i][j][1]);
            atomicAdd(&sAcc[(m + 8) * 49 + n],     acc[i][j][2]);
            atomicAdd(&sAcc[(m + 8) * 49 + n + 1], acc[i][j][3]);
        }
    }
    __syncthreads();
    float* dst = attn + (size_t)(b * HEADS + h) * CH * CH;
    for (int i = tid; i < CH * CH; i += 256)
        atomicAdd(&dst[i], sAcc[(i / CH) * 49 + (i % CH)]);
}

// ---------------- scale by 1/max(||.||,eps) + temperature, softmax over e ----------------
__global__ void softmaxk(float* __restrict__ attn, const float* __restrict__ ssq,
                         const float* __restrict__ temp)
{
    int gw = blockIdx.x * (blockDim.x / 32) + (threadIdx.x >> 5);
    if (gw >= B * HEADS * CH) return;
    int lane = threadIdx.x & 31;
    int c = gw % CH, bh = gw / CH, h = bh % HEADS, b = bh / HEADS;
    float* row = attn + (size_t)gw * CH;
    float iq = 1.f / fmaxf(sqrtf(ssq[b * 2 * C + h * CH + c]), EPS);
    float t  = temp[h];
    int e0 = lane, e1 = lane + 32;
    float ik0 = 1.f / fmaxf(sqrtf(ssq[b * 2 * C + C + h * CH + e0]), EPS);
    float x0 = row[e0] * iq * ik0 * t;
    float x1 = -1e30f;
    if (e1 < CH) {
        float ik1 = 1.f / fmaxf(sqrtf(ssq[b * 2 * C + C + h * CH + e1]), EPS);
        x1 = row[e1] * iq * ik1 * t;
    }
    float m = fmaxf(x0, x1);
    #pragma unroll
    for (int o = 16; o > 0; o >>= 1) m = fmaxf(m, __shfl_xor_sync(~0u, m, o));
    float ex0 = expf(x0 - m);
    float ex1 = (e1 < CH) ? expf(x1 - m) : 0.f;
    float s = ex0 + ex1;
    #pragma unroll
    for (int o = 16; o > 0; o >>= 1) s += __shfl_xor_sync(~0u, s, o);
    float r = 1.f / s;
    row[e0] = ex0 * r;
    if (e1 < CH) row[e1] = ex1 * r;
}

// ---------------- fuse proj weights with attention ----------------
__global__ __launch_bounds__(192) void fuseW(const float* __restrict__ proj_w,
                                             const float* __restrict__ attn,
                                             __half* __restrict__ w2)
{
    int bh = blockIdx.x;
    int h = bh % HEADS, b = bh / HEADS;
    __shared__ float At[CH][CH];
    const float* am = attn + (size_t)bh * CH * CH;
    for (int i = threadIdx.x; i < CH * CH; i += 192)
        At[i / CH][i % CH] = am[i];
    __syncthreads();

    int o = threadIdx.x;
    float pr[CH];
    #pragma unroll
    for (int c = 0; c < CH; c++) pr[c] = proj_w[(size_t)o * C + h * CH + c];

    __half* dst = w2 + (size_t)b * C * C + (size_t)o * C + h * CH;
    #pragma unroll 4
    for (int e = 0; e < CH; e++) {
        float acc = 0.f;
        #pragma unroll
        for (int c = 0; c < CH; c++) acc += pr[c] * At[c][e];
        dst[e] = __float2half_rn(acc);
    }
}

// ---------------- launch ----------------
extern "C" void kernel_launch(void* const* d_in, const int* in_sizes, int n_in,
                              void* d_out, int out_size)
{
    const float* x      = (const float*)d_in[0];
    const float* qkv_w  = (const float*)d_in[1];
    const float* qkv_b  = (const float*)d_in[2];
    const float* dw_w   = (const float*)d_in[3];
    const float* dw_b   = (const float*)d_in[4];
    const float* proj_w = (const float*)d_in[5];
    const float* proj_b = (const float*)d_in[6];
    const float* temp   = (const float*)d_in[7];
    float* out = (float*)d_out;

    float *qkv, *ssqp, *atp;
    __half *qkhp, *qklp, *vhp, *whp, *w2p;
    cudaGetSymbolAddress((void**)&qkv,  g_qkv);
    cudaGetSymbolAddress((void**)&qkhp, g_qkh);
    cudaGetSymbolAddress((void**)&qklp, g_qkl);
    cudaGetSymbolAddress((void**)&vhp,  g_vh);
    cudaGetSymbolAddress((void**)&ssqp, g_ssq);
    cudaGetSymbolAddress((void**)&atp,  g_at);
    cudaGetSymbolAddress((void**)&whp,  g_wh);
    cudaGetSymbolAddress((void**)&w2p,  g_w2h);

    cudaFuncSetAttribute(qk_mma, cudaFuncAttributeMaxDynamicSharedMemorySize, QK_SMEM);

    // 0) qkv weights -> fp16, zero attn accumulator
    cvtW<<<(C3 * C + B * HEADS * CH * CH + 255) / 256, 256>>>(qkv_w, whp, atp);
    // 1) qkv 1x1 conv (fp16 tensor core)
    gemm_mma<0><<<dim3(NPTS / BNg, C3 / BMg, B), 512>>>(
        x, (size_t)C * NPTS, whp, 0, qkv_b, qkv, (size_t)C3 * NPTS);
    // 2) depthwise 3x3x3 -> fp16 hi/lo q,k + fp16 v (+ ssq)
    dwconv3<<<B * C3, 256>>>(qkv, dw_w, dw_b, qkhp, qklp, vhp, ssqp);
    // 3) q @ k^T via fp16 hi/lo tensor cores
    qk_mma<<<dim3(QK_NSPL, HEADS, B), 256, QK_SMEM>>>(qkhp, qklp, atp);
    // 4) scale + softmax
    softmaxk<<<(B * HEADS * CH + 7) / 8, 256>>>(atp, ssqp, temp);
    // 5) fuse proj with attention
    fuseW<<<B * HEADS, 192>>>(proj_w, atp, w2p);
    // 6) fused (proj∘attn) @ v (fp16 v read directly)
    gemm_mma<1><<<dim3(NPTS / BNg, 1, B), 512>>>(
        vhp, (size_t)C * NPTS, w2p, (size_t)C * C, proj_b, out, (size_t)C * NPTS);
}